// round 2
// baseline (speedup 1.0000x reference)
#include <cuda_runtime.h>
#include <cstdint>
#include <cstddef>

// out[b,s,e] = sum_{t<=s} weight[s-t] * x[b,t,e] + bias[s]
// Batched triangular-Toeplitz GEMM, TF32 mma.sync, A-tile synthesized from weight in smem.

#define BM 128
#define BN 128
#define BK 32
#define WMAX 2048
#define PITCH 136   // Xs row pitch in floats -> conflict-free B-frag LDS

__device__ __forceinline__ uint32_t f2tf32(float f) {
    uint32_t u;
    asm("cvt.rna.tf32.f32 %0, %1;" : "=r"(u) : "f"(f));
    return u;
}

__device__ __forceinline__ void mma_tf32(float c[4],
                                         uint32_t a0, uint32_t a1, uint32_t a2, uint32_t a3,
                                         uint32_t b0, uint32_t b1) {
    asm volatile(
        "mma.sync.aligned.m16n8k8.row.col.f32.tf32.tf32.f32 "
        "{%0,%1,%2,%3}, {%4,%5,%6,%7}, {%8,%9}, {%0,%1,%2,%3};"
        : "+f"(c[0]), "+f"(c[1]), "+f"(c[2]), "+f"(c[3])
        : "r"(a0), "r"(a1), "r"(a2), "r"(a3), "r"(b0), "r"(b1));
}

__global__ __launch_bounds__(256, 2)
void toeplitz_kernel(const float* __restrict__ x,
                     const float* __restrict__ weight,
                     const float* __restrict__ bias,
                     float* __restrict__ out,
                     int T, int E)
{
    __shared__ uint32_t wbuf[WMAX];        // tf32-converted weight vector
    __shared__ uint32_t Xs[BK][PITCH];     // tf32-converted x tile [t, e]

    const int tid   = threadIdx.x;
    const int lane  = tid & 31;
    const int wid   = tid >> 5;
    const int warp_m = wid & 1;            // 2 warps along M (s)
    const int warp_n = wid >> 1;           // 4 warps along N (e)
    const int group = lane >> 2;           // 0..7
    const int tg    = lane & 3;            // 0..3

    const int e0 = blockIdx.x * BN;
    const int s0 = blockIdx.y * BM;
    const int b  = blockIdx.z;

    // Stage weight -> smem as tf32 once
    for (int i = tid; i < T; i += 256)
        wbuf[i] = f2tf32(weight[i]);
    __syncthreads();

    float acc[4][4][4];
    #pragma unroll
    for (int mi = 0; mi < 4; ++mi)
        #pragma unroll
        for (int ni = 0; ni < 4; ++ni)
            #pragma unroll
            for (int r = 0; r < 4; ++r)
                acc[mi][ni][r] = 0.0f;

    const float* xb = x + (size_t)b * T * E;
    const int s_warp = s0 + warp_m * 64 + group;   // this lane's base output row
    const int nKiters = 4 * (blockIdx.y + 1);      // triangular skip: only t-blocks <= s-block

    const int ld_c4 = tid & 31;                    // float4 column
    const int ld_r  = tid >> 5;                    // base row (0..7)

    for (int kt = 0; kt < nKiters; ++kt) {
        const int t0 = kt * BK;

        __syncthreads();   // previous tile fully consumed
        {
            const float* src = xb + (size_t)t0 * E + e0 + ld_c4 * 4;
            #pragma unroll
            for (int j = 0; j < 4; ++j) {
                const int row = ld_r + 8 * j;
                float4 v = *reinterpret_cast<const float4*>(src + (size_t)row * E);
                uint4 u;
                u.x = f2tf32(v.x); u.y = f2tf32(v.y);
                u.z = f2tf32(v.z); u.w = f2tf32(v.w);
                *reinterpret_cast<uint4*>(&Xs[row][ld_c4 * 4]) = u;
            }
        }
        __syncthreads();

        #pragma unroll
        for (int ki = 0; ki < 4; ++ki) {
            const int tk = t0 + ki * 8 + tg;

            // B fragments (shared across mi)
            uint32_t bf[4][2];
            #pragma unroll
            for (int ni = 0; ni < 4; ++ni) {
                const int ec = warp_n * 32 + ni * 8 + group;
                bf[ni][0] = Xs[ki * 8 + tg][ec];
                bf[ni][1] = Xs[ki * 8 + tg + 4][ec];
            }

            #pragma unroll
            for (int mi = 0; mi < 4; ++mi) {
                // A fragment synthesized from the Toeplitz vector, causal-masked
                const int dd = s_warp + mi * 16 - tk;      // s - t for a0
                const uint32_t a0 = (dd >= 0)  ? wbuf[dd]     : 0u;  // (row,   k)
                const uint32_t a1 = (dd >= -8) ? wbuf[dd + 8] : 0u;  // (row+8, k)
                const uint32_t a2 = (dd >= 4)  ? wbuf[dd - 4] : 0u;  // (row,   k+4)
                const uint32_t a3 = (dd >= -4) ? wbuf[dd + 4] : 0u;  // (row+8, k+4)

                #pragma unroll
                for (int ni = 0; ni < 4; ++ni)
                    mma_tf32(acc[mi][ni], a0, a1, a2, a3, bf[ni][0], bf[ni][1]);
            }
        }
    }

    // Epilogue: + bias[s], write float2 pairs (cols 2*tg, 2*tg+1)
    float* ob = out + (size_t)b * T * E;
    #pragma unroll
    for (int mi = 0; mi < 4; ++mi) {
        const int r0 = s_warp + mi * 16;
        const int r1 = r0 + 8;
        const float bz0 = __ldg(bias + r0);
        const float bz1 = __ldg(bias + r1);
        #pragma unroll
        for (int ni = 0; ni < 4; ++ni) {
            const int c = e0 + warp_n * 32 + ni * 8 + tg * 2;
            float2 v0 = make_float2(acc[mi][ni][0] + bz0, acc[mi][ni][1] + bz0);
            float2 v1 = make_float2(acc[mi][ni][2] + bz1, acc[mi][ni][3] + bz1);
            *reinterpret_cast<float2*>(ob + (size_t)r0 * E + c) = v0;
            *reinterpret_cast<float2*>(ob + (size_t)r1 * E + c) = v1;
        }
    }
}

extern "C" void kernel_launch(void* const* d_in, const int* in_sizes, int n_in,
                              void* d_out, int out_size)
{
    const float* x      = (const float*)d_in[0];
    const float* weight = (const float*)d_in[1];
    const float* bias   = (const float*)d_in[2];
    float* out          = (float*)d_out;

    const int T = in_sizes[1];              // 2048
    const int E = in_sizes[0] / ( (out_size / in_sizes[0]) == 1 ? (in_sizes[0] / in_sizes[1] / (in_sizes[0] / (in_sizes[1] * 2048))) : 2048 ) > 0 ? 2048 : 2048; // fixed problem: E = 2048
    const int B = in_sizes[0] / (T * E);    // 8

    dim3 grid(E / BN, T / BM, B);
    toeplitz_kernel<<<grid, 256>>>(x, weight, bias, out, T, E);
}

// round 5
// speedup vs baseline: 1.2016x; 1.2016x over previous
#include <cuda_runtime.h>
#include <cstdint>
#include <cstddef>

// out[b,s,e] = sum_{t<=s} weight[s-t] * x[b,t,e] + bias[s]
// Batched triangular-Toeplitz GEMM, TF32 mma.sync.
// R2: cp.async double-buffered mainloop + register-cached A fragments.

#define BM 128
#define BN 128
#define BK 32
#define WMAX 2048
#define PITCH 136   // Xs row pitch in floats -> conflict-free B-frag LDS

__device__ __forceinline__ uint32_t f2tf32(float f) {
    uint32_t u;
    asm("cvt.rna.tf32.f32 %0, %1;" : "=r"(u) : "f"(f));
    return u;
}

__device__ __forceinline__ void mma_tf32(float c[4],
                                         uint32_t a0, uint32_t a1, uint32_t a2, uint32_t a3,
                                         uint32_t b0, uint32_t b1) {
    asm volatile(
        "mma.sync.aligned.m16n8k8.row.col.f32.tf32.tf32.f32 "
        "{%0,%1,%2,%3}, {%4,%5,%6,%7}, {%8,%9}, {%0,%1,%2,%3};"
        : "+f"(c[0]), "+f"(c[1]), "+f"(c[2]), "+f"(c[3])
        : "r"(a0), "r"(a1), "r"(a2), "r"(a3), "r"(b0), "r"(b1));
}

__device__ __forceinline__ void cp_async16(uint32_t smem_addr, const void* gptr) {
    asm volatile("cp.async.ca.shared.global [%0], [%1], 16;\n"
                 :: "r"(smem_addr), "l"(gptr));
}
__device__ __forceinline__ void cp_commit() {
    asm volatile("cp.async.commit_group;\n" ::: "memory");
}
__device__ __forceinline__ void cp_wait_all() {
    asm volatile("cp.async.wait_group 0;\n" ::: "memory");
}

__global__ __launch_bounds__(256, 2)
void toeplitz_kernel(const float* __restrict__ x,
                     const float* __restrict__ weight,
                     const float* __restrict__ bias,
                     float* __restrict__ out,
                     int T, int E)
{
    __shared__ uint32_t wbuf[WMAX];           // tf32-converted weight vector
    __shared__ float Xs[2][BK][PITCH];        // raw fp32 x tiles, double buffered

    const int tid    = threadIdx.x;
    const int lane   = tid & 31;
    const int wid    = tid >> 5;
    const int warp_m = wid & 1;               // 2 warps along M (s)
    const int warp_n = wid >> 1;              // 4 warps along N (e)
    const int group  = lane >> 2;             // 0..7
    const int tg     = lane & 3;              // 0..3

    const int e0 = blockIdx.x * BN;
    const int s0 = blockIdx.y * BM;
    const int b  = blockIdx.z;

    // Stage weight -> smem as tf32 once
    for (int i = tid; i < T; i += 256)
        wbuf[i] = f2tf32(weight[i]);

    float acc[4][4][4];
    #pragma unroll
    for (int mi = 0; mi < 4; ++mi)
        #pragma unroll
        for (int ni = 0; ni < 4; ++ni)
            #pragma unroll
            for (int r = 0; r < 4; ++r)
                acc[mi][ni][r] = 0.0f;

    const float* xb = x + (size_t)b * T * E;
    const int s_warp  = s0 + warp_m * 64 + group;  // this lane's base output row
    const int nKiters = 4 * (blockIdx.y + 1);      // triangular skip

    // loader mapping: each thread does 4 x 16B cp.async
    const int ld_c4 = tid & 31;                    // float4 column 0..31
    const int ld_r  = tid >> 5;                    // base row 0..7

    // Prologue: prefetch tile 0 into buffer 0
    {
        const float* src = xb + e0 + ld_c4 * 4;
        #pragma unroll
        for (int j = 0; j < 4; ++j) {
            const int row = ld_r + 8 * j;
            uint32_t dst = (uint32_t)__cvta_generic_to_shared(&Xs[0][row][ld_c4 * 4]);
            cp_async16(dst, src + (size_t)row * E);
        }
        cp_commit();
    }
    __syncthreads();   // also covers wbuf fill

    for (int kt = 0; kt < nKiters; ++kt) {
        const int t0  = kt * BK;
        const int cur = kt & 1;

        cp_wait_all();       // tile kt landed (this thread's groups)
        __syncthreads();     // visible CTA-wide; all warps done with buffer cur^1

        // Prefetch tile kt+1 into the other buffer
        if (kt + 1 < nKiters) {
            const float* src = xb + (size_t)(t0 + BK) * E + e0 + ld_c4 * 4;
            #pragma unroll
            for (int j = 0; j < 4; ++j) {
                const int row = ld_r + 8 * j;
                uint32_t dst = (uint32_t)__cvta_generic_to_shared(&Xs[cur ^ 1][row][ld_c4 * 4]);
                cp_async16(dst, src + (size_t)row * E);
            }
            cp_commit();
        }

        // A-fragment cache: all 64 fragment values for this tile live in
        // wbuf[D0 + 4j - 28], j = 0..21  (max index = 1991 + 56 = 2047, in range)
        const int D0 = s_warp - t0 - tg;
        uint32_t wv[22];
        #pragma unroll
        for (int j = 0; j < 22; ++j) {
            const int idx = D0 + 4 * j - 28;
            wv[j] = (idx >= 0) ? wbuf[idx] : 0u;
        }

        #pragma unroll
        for (int ki = 0; ki < 4; ++ki) {
            // B fragments from raw fp32 smem, tf32-convert at read
            uint32_t bf[4][2];
            #pragma unroll
            for (int ni = 0; ni < 4; ++ni) {
                const int ec = warp_n * 32 + ni * 8 + group;
                bf[ni][0] = f2tf32(Xs[cur][ki * 8 + tg][ec]);
                bf[ni][1] = f2tf32(Xs[cur][ki * 8 + tg + 4][ec]);
            }

            #pragma unroll
            for (int mi = 0; mi < 4; ++mi) {
                const int jb = 4 * mi - 2 * ki;
                const uint32_t a0 = wv[jb + 7];
                const uint32_t a1 = wv[jb + 9];
                const uint32_t a2 = wv[jb + 6];
                const uint32_t a3 = wv[jb + 8];
                #pragma unroll
                for (int ni = 0; ni < 4; ++ni)
                    mma_tf32(acc[mi][ni], a0, a1, a2, a3, bf[ni][0], bf[ni][1]);
            }
        }
    }

    // Epilogue: + bias[s], write float2 pairs (cols 2*tg, 2*tg+1)
    float* ob = out + (size_t)b * T * E;
    #pragma unroll
    for (int mi = 0; mi < 4; ++mi) {
        const int r0 = s_warp + mi * 16;
        const int r1 = r0 + 8;
        const float bz0 = __ldg(bias + r0);
        const float bz1 = __ldg(bias + r1);
        #pragma unroll
        for (int ni = 0; ni < 4; ++ni) {
            const int c = e0 + warp_n * 32 + ni * 8 + tg * 2;
            float2 v0 = make_float2(acc[mi][ni][0] + bz0, acc[mi][ni][1] + bz0);
            float2 v1 = make_float2(acc[mi][ni][2] + bz1, acc[mi][ni][3] + bz1);
            *reinterpret_cast<float2*>(ob + (size_t)r0 * E + c) = v0;
            *reinterpret_cast<float2*>(ob + (size_t)r1 * E + c) = v1;
        }
    }
}

extern "C" void kernel_launch(void* const* d_in, const int* in_sizes, int n_in,
                              void* d_out, int out_size)
{
    const float* x      = (const float*)d_in[0];
    const float* weight = (const float*)d_in[1];
    const float* bias   = (const float*)d_in[2];
    float* out          = (float*)d_out;

    const int T = in_sizes[1];              // 2048
    const int E = 2048;
    const int B = in_sizes[0] / (T * E);    // 8

    dim3 grid(E / BN, T / BM, B);
    toeplitz_kernel<<<grid, 256>>>(x, weight, bias, out, T, E);
}

// round 10
// speedup vs baseline: 1.3142x; 1.0937x over previous
#include <cuda_runtime.h>
#include <cstdint>
#include <cstddef>

// out[b,s,e] = sum_{t<=s} weight[s-t] * x[b,t,e] + bias[s]
// Batched triangular-Toeplitz GEMM, TF32 mma.sync.
// R6: conflict-free PITCH=136, unmasked wv fast path off-diagonal,
//     warp-level zero-tile skip, heavy-CTAs-first scheduling.

#define BM 128
#define BN 128
#define BK 32
#define WMAX 2048
#define PITCH 136   // bank = (8*tg + group) % 32 -> conflict-free B-frag LDS

__device__ __forceinline__ uint32_t f2tf32(float f) {
    uint32_t u;
    asm("cvt.rna.tf32.f32 %0, %1;" : "=r"(u) : "f"(f));
    return u;
}

__device__ __forceinline__ void mma_tf32(float c[4],
                                         uint32_t a0, uint32_t a1, uint32_t a2, uint32_t a3,
                                         uint32_t b0, uint32_t b1) {
    asm volatile(
        "mma.sync.aligned.m16n8k8.row.col.f32.tf32.tf32.f32 "
        "{%0,%1,%2,%3}, {%4,%5,%6,%7}, {%8,%9}, {%0,%1,%2,%3};"
        : "+f"(c[0]), "+f"(c[1]), "+f"(c[2]), "+f"(c[3])
        : "r"(a0), "r"(a1), "r"(a2), "r"(a3), "r"(b0), "r"(b1));
}

__device__ __forceinline__ void cp_async16(uint32_t smem_addr, const void* gptr) {
    asm volatile("cp.async.ca.shared.global [%0], [%1], 16;\n"
                 :: "r"(smem_addr), "l"(gptr));
}
__device__ __forceinline__ void cp_commit() {
    asm volatile("cp.async.commit_group;\n" ::: "memory");
}
__device__ __forceinline__ void cp_wait_all() {
    asm volatile("cp.async.wait_group 0;\n" ::: "memory");
}

__global__ __launch_bounds__(256, 2)
void toeplitz_kernel(const float* __restrict__ x,
                     const float* __restrict__ weight,
                     const float* __restrict__ bias,
                     float* __restrict__ out,
                     int T, int E)
{
    __shared__ uint32_t wbuf[WMAX];           // tf32-converted weight vector
    __shared__ float Xs[2][BK][PITCH];        // raw fp32 x tiles, double buffered

    const int tid    = threadIdx.x;
    const int lane   = tid & 31;
    const int wid    = tid >> 5;
    const int warp_m = wid & 1;               // 2 warps along M (s)
    const int warp_n = wid >> 1;              // 4 warps along N (e)
    const int group  = lane >> 2;             // 0..7
    const int tg     = lane & 3;              // 0..3

    const int e0 = blockIdx.x * BN;
    const int by = (int)gridDim.y - 1 - (int)blockIdx.y;   // heavy CTAs first
    const int s0 = by * BM;
    const int b  = blockIdx.z;

    // Stage weight -> smem as tf32 once
    for (int i = tid; i < T; i += 256)
        wbuf[i] = f2tf32(weight[i]);

    float acc[4][4][4];
    #pragma unroll
    for (int mi = 0; mi < 4; ++mi)
        #pragma unroll
        for (int ni = 0; ni < 4; ++ni)
            #pragma unroll
            for (int r = 0; r < 4; ++r)
                acc[mi][ni][r] = 0.0f;

    const float* xb = x + (size_t)b * T * E;
    const int s_base  = s0 + warp_m * 64;          // warp's base output row
    const int s_warp  = s_base + group;            // this lane's base output row
    const int nKiters = 4 * (by + 1);              // triangular skip

    // loader mapping: each thread does 4 x 16B cp.async
    const int ld_c4 = tid & 31;                    // float4 column 0..31
    const int ld_r  = tid >> 5;                    // base row 0..7

    // Prologue: prefetch tile 0 into buffer 0
    {
        const float* src = xb + e0 + ld_c4 * 4;
        #pragma unroll
        for (int j = 0; j < 4; ++j) {
            const int row = ld_r + 8 * j;
            uint32_t dst = (uint32_t)__cvta_generic_to_shared(&Xs[0][row][ld_c4 * 4]);
            cp_async16(dst, src + (size_t)row * E);
        }
        cp_commit();
    }
    __syncthreads();   // also covers wbuf fill

    for (int kt = 0; kt < nKiters; ++kt) {
        const int t0  = kt * BK;
        const int cur = kt & 1;

        cp_wait_all();       // tile kt landed
        __syncthreads();     // visible CTA-wide; all warps done with buffer cur^1

        // Prefetch tile kt+1 into the other buffer
        if (kt + 1 < nKiters) {
            const float* src = xb + (size_t)(t0 + BK) * E + e0 + ld_c4 * 4;
            #pragma unroll
            for (int q = 0; q < 4; ++q) {
                const int row = ld_r + 8 * q;
                uint32_t dst = (uint32_t)__cvta_generic_to_shared(&Xs[cur ^ 1][row][ld_c4 * 4]);
                cp_async16(dst, src + (size_t)row * E);
            }
            cp_commit();
        }

        // Warp-level skip: this warp's 64 output rows are all < t0 -> tile is zero
        if (s_base + 63 < t0) continue;

        // A-fragment cache: all 64 fragment values for this tile live in
        // wbuf[D0 + 4j - 28], j = 0..21  (max index = 1991 + 56 = 2047, in range)
        const int D0 = s_warp - t0 - tg;
        uint32_t wv[22];
        if (t0 + 31 < s_base) {
            // off-diagonal: every index >= 0 -> unguarded loads
            #pragma unroll
            for (int j = 0; j < 22; ++j)
                wv[j] = wbuf[D0 + 4 * j - 28];
        } else {
            #pragma unroll
            for (int j = 0; j < 22; ++j) {
                const int idx = D0 + 4 * j - 28;
                wv[j] = (idx >= 0) ? wbuf[idx] : 0u;
            }
        }

        #pragma unroll
        for (int ki = 0; ki < 4; ++ki) {
            // B fragments from raw fp32 smem, tf32-convert at read
            uint32_t bf[4][2];
            #pragma unroll
            for (int ni = 0; ni < 4; ++ni) {
                const int ec = warp_n * 32 + ni * 8 + group;
                bf[ni][0] = f2tf32(Xs[cur][ki * 8 + tg][ec]);
                bf[ni][1] = f2tf32(Xs[cur][ki * 8 + tg + 4][ec]);
            }

            #pragma unroll
            for (int mi = 0; mi < 4; ++mi) {
                const int jb = 4 * mi - 2 * ki;
                const uint32_t a0 = wv[jb + 7];
                const uint32_t a1 = wv[jb + 9];
                const uint32_t a2 = wv[jb + 6];
                const uint32_t a3 = wv[jb + 8];
                #pragma unroll
                for (int ni = 0; ni < 4; ++ni)
                    mma_tf32(acc[mi][ni], a0, a1, a2, a3, bf[ni][0], bf[ni][1]);
            }
        }
    }

    // Epilogue: + bias[s], write float2 pairs (cols 2*tg, 2*tg+1)
    float* ob = out + (size_t)b * T * E;
    #pragma unroll
    for (int mi = 0; mi < 4; ++mi) {
        const int r0 = s_warp + mi * 16;
        const int r1 = r0 + 8;
        const float bz0 = __ldg(bias + r0);
        const float bz1 = __ldg(bias + r1);
        #pragma unroll
        for (int ni = 0; ni < 4; ++ni) {
            const int c = e0 + warp_n * 32 + ni * 8 + tg * 2;
            float2 v0 = make_float2(acc[mi][ni][0] + bz0, acc[mi][ni][1] + bz0);
            float2 v1 = make_float2(acc[mi][ni][2] + bz1, acc[mi][ni][3] + bz1);
            *reinterpret_cast<float2*>(ob + (size_t)r0 * E + c) = v0;
            *reinterpret_cast<float2*>(ob + (size_t)r1 * E + c) = v1;
        }
    }
}

extern "C" void kernel_launch(void* const* d_in, const int* in_sizes, int n_in,
                              void* d_out, int out_size)
{
    const float* x      = (const float*)d_in[0];
    const float* weight = (const float*)d_in[1];
    const float* bias   = (const float*)d_in[2];
    float* out          = (float*)d_out;

    const int T = in_sizes[1];              // 2048
    const int E = 2048;
    const int B = in_sizes[0] / (T * E);    // 8

    dim3 grid(E / BN, T / BM, B);
    toeplitz_kernel<<<grid, 256>>>(x, weight, bias, out, T, E);
}